// round 8
// baseline (speedup 1.0000x reference)
#include <cuda_runtime.h>
#include <cstdint>

#define Bn  2
#define Cn  3
#define OCn 2
#define Hn  96
#define Wn  96
#define Nn  (Hn*Wn)        // 9216
#define NPER (Bn*Nn)       // 18432
#define NCTA 8             // one cluster, grid == cluster
#define NT   768           // 24 warps
#define NW   (NT/32)
#define ROWS 24            // rows per CTA (4 CTAs per batch)

__device__ __forceinline__ uint32_t s2u(const void* p) {
    uint32_t a;
    asm("{ .reg .u64 t; cvta.to.shared.u64 t, %1; cvt.u32.u64 %0, t; }"
        : "=r"(a) : "l"(p));
    return a;
}
// store v into the same smem offset in cluster CTA `rank`
__device__ __forceinline__ void st_peer(uint32_t saddr, int rank, float v) {
    uint32_t r;
    asm volatile("mapa.shared::cluster.u32 %0, %1, %2;" : "=r"(r) : "r"(saddr), "r"(rank));
    asm volatile("st.shared::cluster.f32 [%0], %1;" :: "r"(r), "f"(v) : "memory");
}
#define CLUSTER_ARRIVE() asm volatile("barrier.cluster.arrive.aligned;" ::: "memory")
#define CLUSTER_WAIT()   asm volatile("barrier.cluster.wait.aligned;"   ::: "memory")

__global__ void __launch_bounds__(NT, 1) __cluster_dims__(NCTA, 1, 1)
fused_cluster(const float* __restrict__ q, const float* __restrict__ k,
              const float* __restrict__ w, const float* __restrict__ bias,
              const float* __restrict__ gamma, const float* __restrict__ beta,
              float* __restrict__ out)
{
    __shared__ __align__(16) float sq[Cn][ROWS+2][Wn];  // ~30KB tile + halo
    __shared__ float dmat[144][9];     // dot partials (18 warps x 8 lanes)
    __shared__ float bnmat[192][5];    // BN partials (24 warps x 8 lanes), pad->5
    __shared__ float peerS[NCTA][9];   // written remotely by peers (DSMEM)
    __shared__ float peerBN[NCTA][4];  // written remotely by peers (DSMEM)
    __shared__ float sWp[OCn][Cn][9];  // S-folded effective conv weights
    __shared__ float sstat[4];

    const int t    = threadIdx.x;
    const int bk   = blockIdx.x;       // == cluster rank (grid is one cluster)
    const int lane = t & 31, warp = t >> 5;
    const int b    = bk >> 2;          // batch
    const int r0   = (bk & 3) * ROWS;  // first owned image row
    const float* qb = q + b*Cn*Nn;
    const float* kb = k + b*Cn*Nn;

    // ---- Phase 1a: cooperative q-tile load (26 rows incl halo), float4 ----
    for (int i = t; i < Cn*(ROWS+2)*24; i += NT) {
        const int col4 = i % 24;
        const int rr   = i / 24;
        const int ch   = rr / (ROWS+2);
        const int trow = rr % (ROWS+2);
        const int grow = r0 - 1 + trow;
        float4 v = make_float4(0.f, 0.f, 0.f, 0.f);
        if (grow >= 0 && grow < Hn)
            v = ((const float4*)(qb + ch*Nn + grow*Wn))[col4];
        ((float4*)&sq[ch][trow][0])[col4] = v;
    }
    __syncthreads();

    // ---- Phase 1b: 9 dot partials; q from smem tile, k from global ----
    if (t < 576) {                          // 576 float4 positions per channel
        const int rr = t / 24, c4 = t % 24;
        float4 kk[3], qq[3];
        #pragma unroll
        for (int ch = 0; ch < 3; ch++)
            kk[ch] = ((const float4*)(kb + ch*Nn + (r0+rr)*Wn))[c4];
        #pragma unroll
        for (int ch = 0; ch < 3; ch++)
            qq[ch] = ((const float4*)&sq[ch][rr+1][0])[c4];

        float d[9];
        #pragma unroll
        for (int ch = 0; ch < 3; ch++)
            #pragma unroll
            for (int c = 0; c < 3; c++)
                d[ch*3+c] = kk[ch].x*qq[c].x + kk[ch].y*qq[c].y
                          + kk[ch].z*qq[c].z + kk[ch].w*qq[c].w;
        // 2-level shuffle, then scatter to smem (stride 9 -> conflict-free)
        #pragma unroll
        for (int j = 0; j < 9; j++) {
            d[j] += __shfl_down_sync(0xffffffffu, d[j], 16);
            d[j] += __shfl_down_sync(0xffffffffu, d[j], 8);
        }
        if (lane < 8) {
            #pragma unroll
            for (int j = 0; j < 9; j++) dmat[warp*8 + lane][j] = d[j];
        }
    }
    __syncthreads();

    // 9 warps: strided column sums + final shuffle, then DSMEM broadcast
    if (warp < 9) {
        float v = 0.f;
        #pragma unroll
        for (int i = 0; i < 5; i++) {
            const int row = lane + 32*i;
            if (row < 144) v += dmat[row][warp];
        }
        #pragma unroll
        for (int o = 16; o; o >>= 1) v += __shfl_down_sync(0xffffffffu, v, o);
        if (lane == 0) {
            const uint32_t a = s2u(&peerS[bk][warp]);
            #pragma unroll
            for (int rk = 0; rk < NCTA; rk++) st_peer(a, rk, v);
        }
    }

    // ---- Cluster barrier 1 (release/acquire: DSMEM partials visible) ----
    CLUSTER_ARRIVE();
    CLUSTER_WAIT();

    // ---- Phase 1c: S = sum of my batch's 4 quarters; fold into weights ----
    if (t < OCn*Cn*9) {                 // 54 threads
        const int o   = t / 27;
        const int rem = t % 27;
        const int ch  = rem / 9;
        const int kk  = rem % 9;
        float acc = 0.f;
        #pragma unroll
        for (int c = 0; c < 3; c++) {
            const int j = ch*3 + c;
            const float S = (peerS[b*4+0][j] + peerS[b*4+1][j]
                           + peerS[b*4+2][j] + peerS[b*4+3][j])
                          * 0.57735026918962576451f;   // 1/sqrt(3)
            acc += S * w[(o*Cn + c)*9 + kk];
        }
        sWp[o][ch][kk] = acc;
    }
    __syncthreads();

    // ---- Phase 2: conv from smem tile; 3 contiguous pixels per thread ----
    const int row = t >> 5;            // 0..23 owned row
    const int col = (t & 31) * 3;      // 0,3,...,93
    const float bias0 = bias[0], bias1 = bias[1];
    float y0[3] = {bias0, bias0, bias0};
    float y1[3] = {bias1, bias1, bias1};

    #pragma unroll
    for (int tr = 0; tr < 3; tr++) {
        const int trow = row + tr;
        #pragma unroll
        for (int ch = 0; ch < 3; ch++) {
            float v[5];
            v[0] = (col == 0)  ? 0.f : sq[ch][trow][col-1];
            v[1] = sq[ch][trow][col+0];
            v[2] = sq[ch][trow][col+1];
            v[3] = sq[ch][trow][col+2];
            v[4] = (col == 93) ? 0.f : sq[ch][trow][col+3];
            #pragma unroll
            for (int tc = 0; tc < 3; tc++) {
                const float w0 = sWp[0][ch][tr*3+tc];
                const float w1 = sWp[1][ch][tr*3+tc];
                #pragma unroll
                for (int j = 0; j < 3; j++) {
                    y0[j] += w0 * v[j+tc];
                    y1[j] += w1 * v[j+tc];
                }
            }
        }
    }

    // ---- Phase 2b: BN partials via transpose-reduce + DSMEM broadcast ----
    {
        float s[4] = { y0[0]+y0[1]+y0[2],
                       y1[0]+y1[1]+y1[2],
                       y0[0]*y0[0]+y0[1]*y0[1]+y0[2]*y0[2],
                       y1[0]*y1[0]+y1[1]*y1[1]+y1[2]*y1[2] };
        #pragma unroll
        for (int j = 0; j < 4; j++) {
            s[j] += __shfl_down_sync(0xffffffffu, s[j], 16);
            s[j] += __shfl_down_sync(0xffffffffu, s[j], 8);
        }
        if (lane < 8) {
            #pragma unroll
            for (int j = 0; j < 4; j++) bnmat[warp*8 + lane][j] = s[j];
        }
    }
    __syncthreads();
    if (warp < 4) {
        float v = 0.f;
        #pragma unroll
        for (int i = 0; i < 6; i++) v += bnmat[lane + 32*i][warp];   // 192 rows
        #pragma unroll
        for (int o = 16; o; o >>= 1) v += __shfl_down_sync(0xffffffffu, v, o);
        if (lane == 0) {
            const uint32_t a = s2u(&peerBN[bk][warp]);
            #pragma unroll
            for (int rk = 0; rk < NCTA; rk++) st_peer(a, rk, v);
        }
    }

    // ---- Cluster barrier 2 ----
    CLUSTER_ARRIVE();
    CLUSTER_WAIT();

    if (t < 4) {
        float v = 0.f;
        #pragma unroll
        for (int rk = 0; rk < NCTA; rk++) v += peerBN[rk][t];
        sstat[t] = v;
    }
    __syncthreads();

    // ---- Phase 3: BN (biased var, eps=1e-5) + affine + LeakyReLU(0.1) ----
    const float inv_n = 1.0f / (float)NPER;
    const float mean0 = sstat[0] * inv_n;
    const float mean1 = sstat[1] * inv_n;
    const float var0  = sstat[2] * inv_n - mean0*mean0;
    const float var1  = sstat[3] * inv_n - mean1*mean1;
    const float sc0   = rsqrtf(var0 + 1e-5f) * gamma[0];
    const float sc1   = rsqrtf(var1 + 1e-5f) * gamma[1];
    const float be0   = beta[0], be1 = beta[1];

    float* o0 = out + (b*OCn + 0)*Nn + (r0 + row)*Wn + col;
    float* o1 = out + (b*OCn + 1)*Nn + (r0 + row)*Wn + col;
    #pragma unroll
    for (int j = 0; j < 3; j++) {
        float v0 = (y0[j] - mean0) * sc0 + be0;
        float v1 = (y1[j] - mean1) * sc1 + be1;
        o0[j] = (v0 >= 0.f) ? v0 : 0.1f*v0;
        o1[j] = (v1 >= 0.f) ? v1 : 0.1f*v1;
    }
}

// ---------------------------------------------------------------------------
extern "C" void kernel_launch(void* const* d_in, const int* in_sizes, int n_in,
                              void* d_out, int out_size)
{
    const float* q      = (const float*)d_in[0];  // X_tnext
    const float* k      = (const float*)d_in[1];  // X_hat_tnext
    const float* conv_w = (const float*)d_in[2];
    const float* conv_b = (const float*)d_in[3];
    const float* gamma  = (const float*)d_in[4];
    const float* beta   = (const float*)d_in[5];
    float* out = (float*)d_out;

    fused_cluster<<<NCTA, NT>>>(q, k, conv_w, conv_b, gamma, beta, out);
}

// round 10
// speedup vs baseline: 1.0652x; 1.0652x over previous
#include <cuda_runtime.h>
#include <cstdint>

#define Bn  2
#define Cn  3
#define OCn 2
#define Hn  96
#define Wn  96
#define Nn  (Hn*Wn)        // 9216
#define NPER (Bn*Nn)       // 18432
#define NCTA 8             // one cluster, grid == cluster
#define NT   768           // 24 warps
#define NW   (NT/32)
#define ROWS 24            // rows per CTA (4 CTAs per batch)

__device__ __forceinline__ uint32_t s2u(const void* p) {
    uint32_t a;
    asm("{ .reg .u64 t; cvta.to.shared.u64 t, %1; cvt.u32.u64 %0, t; }"
        : "=r"(a) : "l"(p));
    return a;
}
__device__ __forceinline__ void st_peer(uint32_t saddr, int rank, float v) {
    uint32_t r;
    asm volatile("mapa.shared::cluster.u32 %0, %1, %2;" : "=r"(r) : "r"(saddr), "r"(rank));
    asm volatile("st.shared::cluster.f32 [%0], %1;" :: "r"(r), "f"(v) : "memory");
}
#define CLUSTER_ARRIVE() asm volatile("barrier.cluster.arrive.aligned;" ::: "memory")
#define CLUSTER_WAIT()   asm volatile("barrier.cluster.wait.aligned;"   ::: "memory")

__global__ void __launch_bounds__(NT, 1) __cluster_dims__(NCTA, 1, 1)
fused_cluster(const float* __restrict__ q, const float* __restrict__ k,
              const float* __restrict__ w, const float* __restrict__ bias,
              const float* __restrict__ gamma, const float* __restrict__ beta,
              float* __restrict__ out)
{
    __shared__ __align__(16) float sq[Cn][ROWS+2][Wn];  // ~30KB tile + halo
    __shared__ float dmat[144][9];     // dot partials (18 warps x 8 lanes)
    __shared__ float bnmat[192][5];    // BN partials (24 warps x 8 lanes)
    __shared__ float peerS[NCTA][9];   // DSMEM: written remotely by peers
    __shared__ float peerBN[NCTA][4];  // DSMEM: written remotely by peers
    __shared__ float sw[54];           // raw conv weights (prefetched)
    __shared__ float sWp[OCn][Cn][9];  // S-folded effective conv weights
    __shared__ float sc[6];            // bias0,bias1,g0,g1,be0,be1
    __shared__ float sstat[4];

    const int t    = threadIdx.x;
    const int bk   = blockIdx.x;       // cluster rank
    const int lane = t & 31, warp = t >> 5;
    const int b    = bk >> 2;
    const int r0   = (bk & 3) * ROWS;
    const float* qb = q + b*Cn*Nn;
    const float* kb = k + b*Cn*Nn;

    // ================= Phase 1: ONE parallel load wave ====================
    // threads 0..575 : 3 q-float4 (owned rows, -> regs + smem) + 3 k-float4
    // threads 576..719: halo rows (2 rows x 3ch x 24 f4 = 144)
    // threads 576..629: also conv_w (54);  630..635: bias/gamma/beta
    float4 qq[3], kk[3];
    const int rr = t / 24, c4 = t % 24;        // rr 0..23 for t<576
    if (t < 576) {
        #pragma unroll
        for (int ch = 0; ch < 3; ch++) {
            qq[ch] = ((const float4*)(qb + ch*Nn + (r0+rr)*Wn))[c4];
            kk[ch] = ((const float4*)(kb + ch*Nn + (r0+rr)*Wn))[c4];
        }
        #pragma unroll
        for (int ch = 0; ch < 3; ch++)
            ((float4*)&sq[ch][rr+1][0])[c4] = qq[ch];
    } else {
        const int i     = t - 576;             // 0..191
        if (i < 144) {
            const int ch    = i / 48;
            const int which = (i % 48) / 24;       // 0=top halo, 1=bottom halo
            const int hc4   = i % 24;
            const int grow  = r0 - 1 + which*(ROWS+1);
            float4 v = make_float4(0.f, 0.f, 0.f, 0.f);
            if (grow >= 0 && grow < Hn)
                v = ((const float4*)(qb + ch*Nn + grow*Wn))[hc4];
            ((float4*)&sq[ch][which*(ROWS+1)][0])[hc4] = v;
        }
        if (i < 54) sw[i] = w[i];
        else if (i >= 54 && i < 60) {
            const int j = i - 54;
            sc[j] = (j < 2) ? bias[j] : (j < 4 ? gamma[j-2] : beta[j-4]);
        }
    }

    // ---- dots from registers (no smem dependency) ----
    if (t < 576) {
        float d[9];
        #pragma unroll
        for (int ch = 0; ch < 3; ch++)
            #pragma unroll
            for (int c = 0; c < 3; c++)
                d[ch*3+c] = kk[ch].x*qq[c].x + kk[ch].y*qq[c].y
                          + kk[ch].z*qq[c].z + kk[ch].w*qq[c].w;
        #pragma unroll
        for (int j = 0; j < 9; j++) {
            d[j] += __shfl_down_sync(0xffffffffu, d[j], 16);
            d[j] += __shfl_down_sync(0xffffffffu, d[j], 8);
        }
        if (lane < 8) {
            #pragma unroll
            for (int j = 0; j < 9; j++) dmat[warp*8 + lane][j] = d[j];
        }
    }
    __syncthreads();

    // 9 warps: strided column sums + final shuffle, then DSMEM broadcast
    if (warp < 9) {
        float v = 0.f;
        #pragma unroll
        for (int i = 0; i < 5; i++) {
            const int row = lane + 32*i;
            if (row < 144) v += dmat[row][warp];
        }
        #pragma unroll
        for (int o = 16; o; o >>= 1) v += __shfl_down_sync(0xffffffffu, v, o);
        if (lane == 0) {
            const uint32_t a = s2u(&peerS[bk][warp]);
            #pragma unroll
            for (int rk = 0; rk < NCTA; rk++) st_peer(a, rk, v);
        }
    }

    // ---- Cluster barrier 1 (release/acquire) ----
    CLUSTER_ARRIVE();
    CLUSTER_WAIT();

    // ---- Fold S into effective conv weights (all operands in smem) ----
    if (t < OCn*Cn*9) {                 // 54 threads
        const int o   = t / 27;
        const int rem = t % 27;
        const int ch  = rem / 9;
        const int kkk = rem % 9;
        float acc = 0.f;
        #pragma unroll
        for (int c = 0; c < 3; c++) {
            const int j = ch*3 + c;
            const float S = (peerS[b*4+0][j] + peerS[b*4+1][j]
                           + peerS[b*4+2][j] + peerS[b*4+3][j])
                          * 0.57735026918962576451f;
            acc += S * sw[(o*Cn + c)*9 + kkk];
        }
        sWp[o][ch][kkk] = acc;
    }
    __syncthreads();

    // ---- Phase 2: conv from smem tile; 3 contiguous pixels per thread ----
    const int row = t >> 5;
    const int col = (t & 31) * 3;
    const float bias0 = sc[0], bias1 = sc[1];
    float y0[3] = {bias0, bias0, bias0};
    float y1[3] = {bias1, bias1, bias1};

    #pragma unroll
    for (int tr = 0; tr < 3; tr++) {
        const int trow = row + tr;
        #pragma unroll
        for (int ch = 0; ch < 3; ch++) {
            float v[5];
            v[0] = (col == 0)  ? 0.f : sq[ch][trow][col-1];
            v[1] = sq[ch][trow][col+0];
            v[2] = sq[ch][trow][col+1];
            v[3] = sq[ch][trow][col+2];
            v[4] = (col == 93) ? 0.f : sq[ch][trow][col+3];
            #pragma unroll
            for (int tc = 0; tc < 3; tc++) {
                const float w0 = sWp[0][ch][tr*3+tc];
                const float w1 = sWp[1][ch][tr*3+tc];
                #pragma unroll
                for (int j = 0; j < 3; j++) {
                    y0[j] += w0 * v[j+tc];
                    y1[j] += w1 * v[j+tc];
                }
            }
        }
    }

    // ---- BN partials via transpose-reduce + DSMEM broadcast ----
    {
        float s[4] = { y0[0]+y0[1]+y0[2],
                       y1[0]+y1[1]+y1[2],
                       y0[0]*y0[0]+y0[1]*y0[1]+y0[2]*y0[2],
                       y1[0]*y1[0]+y1[1]*y1[1]+y1[2]*y1[2] };
        #pragma unroll
        for (int j = 0; j < 4; j++) {
            s[j] += __shfl_down_sync(0xffffffffu, s[j], 16);
            s[j] += __shfl_down_sync(0xffffffffu, s[j], 8);
        }
        if (lane < 8) {
            #pragma unroll
            for (int j = 0; j < 4; j++) bnmat[warp*8 + lane][j] = s[j];
        }
    }
    __syncthreads();
    if (warp < 4) {
        float v = 0.f;
        #pragma unroll
        for (int i = 0; i < 6; i++) v += bnmat[lane + 32*i][warp];
        #pragma unroll
        for (int o = 16; o; o >>= 1) v += __shfl_down_sync(0xffffffffu, v, o);
        if (lane == 0) {
            const uint32_t a = s2u(&peerBN[bk][warp]);
            #pragma unroll
            for (int rk = 0; rk < NCTA; rk++) st_peer(a, rk, v);
        }
    }

    // ---- Cluster barrier 2 ----
    CLUSTER_ARRIVE();
    CLUSTER_WAIT();

    if (t < 4) {
        float v = 0.f;
        #pragma unroll
        for (int rk = 0; rk < NCTA; rk++) v += peerBN[rk][t];
        sstat[t] = v;
    }
    __syncthreads();

    // ---- Phase 3: BN + affine + LeakyReLU(0.1) ----
    const float inv_n = 1.0f / (float)NPER;
    const float mean0 = sstat[0] * inv_n;
    const float mean1 = sstat[1] * inv_n;
    const float var0  = sstat[2] * inv_n - mean0*mean0;
    const float var1  = sstat[3] * inv_n - mean1*mean1;
    const float sc0   = rsqrtf(var0 + 1e-5f) * sc[2];
    const float sc1   = rsqrtf(var1 + 1e-5f) * sc[3];
    const float be0   = sc[4], be1 = sc[5];

    float* o0 = out + (b*OCn + 0)*Nn + (r0 + row)*Wn + col;
    float* o1 = out + (b*OCn + 1)*Nn + (r0 + row)*Wn + col;
    #pragma unroll
    for (int j = 0; j < 3; j++) {
        float v0 = (y0[j] - mean0) * sc0 + be0;
        float v1 = (y1[j] - mean1) * sc1 + be1;
        o0[j] = (v0 >= 0.f) ? v0 : 0.1f*v0;
        o1[j] = (v1 >= 0.f) ? v1 : 0.1f*v1;
    }
}

// ---------------------------------------------------------------------------
extern "C" void kernel_launch(void* const* d_in, const int* in_sizes, int n_in,
                              void* d_out, int out_size)
{
    const float* q      = (const float*)d_in[0];  // X_tnext
    const float* k      = (const float*)d_in[1];  // X_hat_tnext
    const float* conv_w = (const float*)d_in[2];
    const float* conv_b = (const float*)d_in[3];
    const float* gamma  = (const float*)d_in[4];
    const float* beta   = (const float*)d_in[5];
    float* out = (float*)d_out;

    fused_cluster<<<NCTA, NT>>>(q, k, conv_w, conv_b, gamma, beta, out);
}